// round 17
// baseline (speedup 1.0000x reference)
#include <cuda_runtime.h>
#include <math.h>

#define EPS 1e-5f
typedef unsigned long long u64;

// ---------------- f32x2 helpers ----------------
__device__ __forceinline__ u64 pack2(float a, float b) {
    u64 r; asm("mov.b64 %0,{%1,%2};" : "=l"(r) : "f"(a), "f"(b)); return r;
}
__device__ __forceinline__ void unpack2(u64 v, float &a, float &b) {
    asm("mov.b64 {%0,%1},%2;" : "=f"(a), "=f"(b) : "l"(v));
}
__device__ __forceinline__ u64 fma2(u64 a, u64 b, u64 c) {
    u64 d; asm("fma.rn.f32x2 %0,%1,%2,%3;" : "=l"(d) : "l"(a), "l"(b), "l"(c)); return d;
}

// ---------------- fast exact-erf GELU (A&S 7.1.26, |erf err| < 1.5e-7) ----
__device__ __forceinline__ float gelu1(float v) {
    float ax = fabsf(v) * 0.70710678118654752440f;
    float d  = fmaf(0.3275911f, ax, 1.0f);
    float t; asm("rcp.approx.f32 %0,%1;" : "=f"(t) : "f"(d));
    float p = fmaf(1.061405429f, t, -1.453152027f);
    p = fmaf(p, t, 1.421413741f);
    p = fmaf(p, t, -0.284496736f);
    p = fmaf(p, t, 0.254829592f);
    p = p * t;
    float e = __expf(-ax * ax);
    float er = fmaf(-p, e, 1.0f);
    er = copysignf(er, v);
    return 0.5f * v * (1.0f + er);
}

// ===========================================================================
// FUSED kernel: per 16x8 tile CTA (512 thr, 1 CTA/SM):
//   1. load x halo (22x14 x 32ch) -> smem
//   2. conv1+GELU in-tile for ALL 308 halo pixels -> x1s smem (2.4x redundant)
//   3. reduce r = relu(bn(wr@x1)) for OWN pixel (x1s[hpo], j-quad per group)
//   4. span-JIT involution + BN1 + GELU
//   5. y-exchange, conv2(BN2 folded) with skip (BN-folded wm @ x-from-smem)
//      interleaved into the same accumulators, + GELU -> out
// No intermediate global scratch at all.
// ===========================================================================
#define TW 16
#define TH 8
#define HW 22
#define HP 308            // 22*14 halo pixels
#define CSTR 68           // x1 channel stride (conflict-free LDS.128)
#define XSTR 33           // x halo channel stride (odd -> conflict-free scalar)

#define S_XS    0                         // 308*33  = 10164
#define S_X1S   (S_XS + HP * XSTR)        // 10164, size 20944
#define S_W1N   (S_X1S + HP * CSTR)       // 31108, size 2048  [ci][o]
#define S_WRN   (S_W1N + 2048)            // 33156, size 1024  [c][j]
#define S_WMT   (S_WRN + 1024)            // 34180, size 2048  [ci][o]*sm
#define S_W2T   (S_WMT + 2048)            // 36228, size 4096  [c][o]*s2
#define S_WSS   (S_W2T + 4096)            // 40324, size 3584  [g][di][j][8]
#define S_RBUF  (S_WSS + 3584)            // 43908, size 2176  [128][17]
#define S_S1V   (S_RBUF + 2176)           // 46084
#define S_T1V   (S_S1V + 64)
#define S_T2V   (S_T1V + 64)              // combined conv2-bn + skip-bn bias
#define S_SRV   (S_T2V + 64)
#define S_TRV   (S_SRV + 16)
#define S_TOTAL (S_TRV + 16)              // 46308 floats
#define SMEM_BYTES (S_TOTAL * 4)          // 185232 B -> 1 CTA/SM

extern __shared__ __align__(16) float smem[];

__global__ void __launch_bounds__(512, 1) k_fused(
    const float* __restrict__ x,
    const float* __restrict__ w1,
    const float* __restrict__ wr, const float* __restrict__ gr,
    const float* __restrict__ br, const float* __restrict__ mr,
    const float* __restrict__ vr,
    const float* __restrict__ ws, const float* __restrict__ bs,
    const float* __restrict__ g1, const float* __restrict__ b1,
    const float* __restrict__ m1, const float* __restrict__ v1,
    const float* __restrict__ w2, const float* __restrict__ g2,
    const float* __restrict__ b2, const float* __restrict__ m2,
    const float* __restrict__ v2,
    const float* __restrict__ wm, const float* __restrict__ bmap,
    const float* __restrict__ gm, const float* __restrict__ betam,
    const float* __restrict__ mm, const float* __restrict__ vm,
    float* __restrict__ out)
{
    float* xs  = smem + S_XS;
    float* x1s = smem + S_X1S;
    float* w1n = smem + S_W1N;
    float* wrn = smem + S_WRN;
    float* wmt = smem + S_WMT;
    float* w2t = smem + S_W2T;
    float* wss = smem + S_WSS;
    float* rbuf = smem + S_RBUF;
    float* s1v = smem + S_S1V;
    float* t1v = smem + S_T1V;
    float* t2v = smem + S_T2V;
    float* srv = smem + S_SRV;
    float* trv = smem + S_TRV;

    const int tid = threadIdx.x;
    const int b = blockIdx.z;
    const int tx0 = blockIdx.x * TW, ty0 = blockIdx.y * TH;

    // ---- prologue: weights ----
    for (int i = tid; i < 2048; i += 512) {
        int ci = i >> 6, o = i & 63;
        w1n[i] = w1[o * 32 + ci];
        float s = gm[o] * rsqrtf(vm[o] + EPS);
        wmt[i] = wm[o * 32 + ci] * s;
    }
    for (int i = tid; i < 1024; i += 512) {
        int c = i >> 4, j = i & 15;
        wrn[i] = wr[j * 64 + c];
    }
    for (int i = tid; i < 4096; i += 512) {
        int c = i >> 6, o = i & 63;
        float s2 = g2[o] * rsqrtf(v2[o] + EPS);
        w2t[i] = w2[o * 64 + c] * s2;
    }
    for (int i = tid; i < 3584; i += 512) {
        int dj = i & 7, j = (i >> 3) & 15, gd = i >> 7;
        int di = gd % 7, gq = gd / 7;
        wss[i] = (dj < 7) ? ws[(gq * 49 + di * 7 + dj) * 16 + j] : 0.f;
    }
    if (tid < 64) {
        float s1 = g1[tid] * rsqrtf(v1[tid] + EPS);
        s1v[tid] = s1; t1v[tid] = b1[tid] - m1[tid] * s1;
        float s2 = g2[tid] * rsqrtf(v2[tid] + EPS);
        float sm = gm[tid] * rsqrtf(vm[tid] + EPS);
        // combined bias: conv2-bn shift + folded skip-bn shift
        t2v[tid] = (b2[tid] - m2[tid] * s2)
                 + fmaf(sm, bmap[tid], betam[tid]) - mm[tid] * sm;
    }
    if (tid < 16) {
        float s = gr[tid] * rsqrtf(vr[tid] + EPS);
        srv[tid] = s; trv[tid] = br[tid] - mr[tid] * s;
    }

    // ---- load x halo (zero padded): xs[hp*33 + c] ----
    const float* xb = x + ((size_t)b << 19);
    for (int i = tid; i < HP * 32; i += 512) {
        int c = i / HP, hp = i - c * HP;
        int hy = hp / HW, hx = hp - hy * HW;
        int gy = ty0 - 3 + hy, gx = tx0 - 3 + hx;
        float v = 0.f;
        if (gy >= 0 && gy < 128 && gx >= 0 && gx < 128)
            v = __ldg(xb + ((size_t)c << 14) + (gy << 7) + gx);
        xs[hp * XSTR + c] = v;
    }
    __syncthreads();

    // ---- conv1 + GELU for all halo pixels (task = cg*308 + hp) ----
    for (int task = tid; task < HP * 4; task += 512) {
        int cg = task / HP, hp = task - cg * HP;
        float xv[32];
#pragma unroll
        for (int ci = 0; ci < 32; ci++) xv[ci] = xs[hp * XSTR + ci];
        u64 acc[8];
#pragma unroll
        for (int q = 0; q < 8; q++) acc[q] = 0ull;
#pragma unroll 4
        for (int ci = 0; ci < 32; ci++) {
            u64 xd = pack2(xv[ci], xv[ci]);
            const ulonglong2* wp = (const ulonglong2*)(w1n + ci * 64 + cg * 16);
#pragma unroll
            for (int q = 0; q < 4; q++) {
                ulonglong2 w = wp[q];
                acc[2 * q]     = fma2(w.x, xd, acc[2 * q]);
                acc[2 * q + 1] = fma2(w.y, xd, acc[2 * q + 1]);
            }
        }
        float* x1d = x1s + hp * CSTR + cg * 16;
#pragma unroll
        for (int k = 0; k < 4; k++) {
            float a0, a1, b0, b1;
            unpack2(acc[2 * k], a0, a1); unpack2(acc[2 * k + 1], b0, b1);
            ((float4*)x1d)[k] = make_float4(gelu1(a0), gelu1(a1), gelu1(b0), gelu1(b1));
        }
    }
    __syncthreads();

    const int p = tid & 127, g = tid >> 7;
    const int py = p >> 4, px = p & 15;
    const int gy = ty0 + py, gx = tx0 + px;
    const int pix = (gy << 7) + gx;
    const int ch0 = g * 16;
    const int hpo = (py + 3) * HW + (px + 3);        // own pixel in halo coords

    // ---- reduce r: this thread computes j-quad [4g, 4g+4) for OWN pixel ----
    {
        u64 racc0 = 0ull, racc1 = 0ull;
        const u64* x1p = (const u64*)(x1s + hpo * CSTR);   // R17 FIX: was p*CSTR
#pragma unroll 8
        for (int cp = 0; cp < 32; cp++) {
            float c0, c1; unpack2(x1p[cp], c0, c1);
            ulonglong2 wA = *(const ulonglong2*)(wrn + (2 * cp) * 16 + 4 * g);
            ulonglong2 wB = *(const ulonglong2*)(wrn + (2 * cp + 1) * 16 + 4 * g);
            u64 d0 = pack2(c0, c0), d1 = pack2(c1, c1);
            racc0 = fma2(wA.x, d0, racc0); racc1 = fma2(wA.y, d0, racc1);
            racc0 = fma2(wB.x, d1, racc0); racc1 = fma2(wB.y, d1, racc1);
        }
        float j0, j1, j2, j3;
        unpack2(racc0, j0, j1); unpack2(racc1, j2, j3);
        int jb = 4 * g;
        rbuf[p * 17 + jb + 0] = fmaxf(fmaf(srv[jb + 0], j0, trv[jb + 0]), 0.f);
        rbuf[p * 17 + jb + 1] = fmaxf(fmaf(srv[jb + 1], j1, trv[jb + 1]), 0.f);
        rbuf[p * 17 + jb + 2] = fmaxf(fmaf(srv[jb + 2], j2, trv[jb + 2]), 0.f);
        rbuf[p * 17 + jb + 3] = fmaxf(fmaf(srv[jb + 3], j3, trv[jb + 3]), 0.f);
    }
    __syncthreads();
    float r16[16];
#pragma unroll
    for (int j = 0; j < 16; j++) r16[j] = rbuf[p * 17 + j];

    // ---- involution with JIT span-weight generation ----
    u64 acc[8];
#pragma unroll
    for (int q = 0; q < 8; q++) acc[q] = 0ull;
#pragma unroll
    for (int di = 0; di < 7; di++) {
        const float* bsp = bs + g * 49 + di * 7;     // warp-uniform
        u64 wa[4];
        wa[0] = pack2(__ldg(bsp + 0), __ldg(bsp + 1));
        wa[1] = pack2(__ldg(bsp + 2), __ldg(bsp + 3));
        wa[2] = pack2(__ldg(bsp + 4), __ldg(bsp + 5));
        wa[3] = pack2(__ldg(bsp + 6), 0.f);
        const ulonglong2* wsp = (const ulonglong2*)(wss + ((g * 7 + di) * 16) * 8);
#pragma unroll
        for (int j = 0; j < 16; j++) {
            u64 rd = pack2(r16[j], r16[j]);
            ulonglong2 wA = wsp[2 * j];
            ulonglong2 wB = wsp[2 * j + 1];
            wa[0] = fma2(wA.x, rd, wa[0]);
            wa[1] = fma2(wA.y, rd, wa[1]);
            wa[2] = fma2(wB.x, rd, wa[2]);
            wa[3] = fma2(wB.y, rd, wa[3]);
        }
        float w7[8];
        unpack2(wa[0], w7[0], w7[1]); unpack2(wa[1], w7[2], w7[3]);
        unpack2(wa[2], w7[4], w7[5]); unpack2(wa[3], w7[6], w7[7]);

        const float* rowb = x1s + ((py + di) * HW + px) * CSTR + ch0;
#pragma unroll
        for (int dj = 0; dj < 7; dj++) {
            u64 kp = pack2(w7[dj], w7[dj]);
            const ulonglong2* xp = (const ulonglong2*)(rowb + dj * CSTR);
#pragma unroll
            for (int q = 0; q < 4; q++) {
                ulonglong2 xv = xp[q];
                acc[2 * q]     = fma2(kp, xv.x, acc[2 * q]);
                acc[2 * q + 1] = fma2(kp, xv.y, acc[2 * q + 1]);
            }
        }
    }
    // BN1 + GELU
    float y[16];
#pragma unroll
    for (int q = 0; q < 8; q++) {
        u64 s = *(const u64*)(s1v + ch0 + 2 * q);
        u64 t = *(const u64*)(t1v + ch0 + 2 * q);
        u64 v = fma2(acc[q], s, t);
        float a0, a1; unpack2(v, a0, a1);
        y[2 * q] = gelu1(a0); y[2 * q + 1] = gelu1(a1);
    }

    // ---- exchange y through x1s rows 0..127 (involution reads done) ----
    __syncthreads();
#pragma unroll
    for (int c = 0; c < 16; c++) x1s[p * CSTR + ch0 + c] = y[c];
    __syncthreads();

    // ---- conv2 (bn2 folded) + skip (bn folded, from xs) interleaved ----
    u64 acc2[8];
#pragma unroll
    for (int q = 0; q < 8; q++) acc2[q] = *(const u64*)(t2v + ch0 + 2 * q);
    const float4* yb = (const float4*)(x1s + p * CSTR);
#pragma unroll 4
    for (int c4 = 0; c4 < 16; c4++) {
        float4 yv = yb[c4];
        float ya[4] = { yv.x, yv.y, yv.z, yv.w };
#pragma unroll
        for (int cc = 0; cc < 4; cc++) {
            int c = c4 * 4 + cc;
            u64 yp2 = pack2(ya[cc], ya[cc]);
            const ulonglong2* wp = (const ulonglong2*)(w2t + c * 64 + ch0);
#pragma unroll
            for (int q = 0; q < 4; q++) {
                ulonglong2 w = wp[q];
                acc2[2 * q]     = fma2(w.x, yp2, acc2[2 * q]);
                acc2[2 * q + 1] = fma2(w.y, yp2, acc2[2 * q + 1]);
            }
        }
    }
    {
        const float* xso = xs + hpo * XSTR;
#pragma unroll 4
        for (int ci = 0; ci < 32; ci++) {
            float xc = xso[ci];
            u64 xd = pack2(xc, xc);
            const ulonglong2* wp = (const ulonglong2*)(wmt + ci * 64 + ch0);
#pragma unroll
            for (int q = 0; q < 4; q++) {
                ulonglong2 w = wp[q];
                acc2[2 * q]     = fma2(w.x, xd, acc2[2 * q]);
                acc2[2 * q + 1] = fma2(w.y, xd, acc2[2 * q + 1]);
            }
        }
    }
    // ---- GELU + store ----
    float* ob = out + ((size_t)b << 20) + pix;
#pragma unroll
    for (int q = 0; q < 8; q++) {
        float a0, a1; unpack2(acc2[q], a0, a1);
        int o0 = ch0 + 2 * q;
        ob[(size_t)o0 << 14]       = gelu1(a0);
        ob[(size_t)(o0 + 1) << 14] = gelu1(a1);
    }
}

// ===========================================================================
// Launch. Input order: x w1 wr gr br mr vr ws bs g1 b1 m1 v1
//                      w2 g2 b2 m2 v2 wm bmap gm betam mm vm
// ===========================================================================
extern "C" void kernel_launch(void* const* d_in, const int* in_sizes, int n_in,
                              void* d_out, int out_size)
{
    (void)in_sizes; (void)n_in; (void)out_size;
    const float* x     = (const float*)d_in[0];
    const float* w1    = (const float*)d_in[1];
    const float* wr    = (const float*)d_in[2];
    const float* gr    = (const float*)d_in[3];
    const float* br    = (const float*)d_in[4];
    const float* mr    = (const float*)d_in[5];
    const float* vr    = (const float*)d_in[6];
    const float* ws    = (const float*)d_in[7];
    const float* bs    = (const float*)d_in[8];
    const float* g1    = (const float*)d_in[9];
    const float* b1    = (const float*)d_in[10];
    const float* m1    = (const float*)d_in[11];
    const float* v1    = (const float*)d_in[12];
    const float* w2    = (const float*)d_in[13];
    const float* g2    = (const float*)d_in[14];
    const float* b2    = (const float*)d_in[15];
    const float* m2    = (const float*)d_in[16];
    const float* v2    = (const float*)d_in[17];
    const float* wm    = (const float*)d_in[18];
    const float* bmap  = (const float*)d_in[19];
    const float* gm    = (const float*)d_in[20];
    const float* betam = (const float*)d_in[21];
    const float* mm    = (const float*)d_in[22];
    const float* vm    = (const float*)d_in[23];
    float* out = (float*)d_out;

    cudaFuncSetAttribute(k_fused, cudaFuncAttributeMaxDynamicSharedMemorySize,
                         SMEM_BYTES);
    k_fused<<<dim3(128 / TW, 128 / TH, 4), 512, SMEM_BYTES>>>(
        x, w1, wr, gr, br, mr, vr, ws, bs,
        g1, b1, m1, v1, w2, g2, b2, m2, v2,
        wm, bmap, gm, betam, mm, vm, out);
}